// round 10
// baseline (speedup 1.0000x reference)
#include <cuda_runtime.h>
#include <cuda_bf16.h>
#include <cstdint>

#define B_   8
#define H_   16
#define S_   1024
#define D_   64
#define BH_  (B_*H_)
#define NT   256
#define NCH  16            // 64-col chunks

#define OUT_O ((size_t)BH_*S_*D_)
#define OUT_W ((size_t)BH_*S_*S_)

// pre-swizzled bf16 hi/lo MMA-ready tiles: 16KB per (bh, chunk)
__device__ uint4 g_Kst[BH_*NCH*1024];   // K tile: [64 s][64 d]
__device__ uint4 g_Vst[BH_*NCH*1024];   // V tile: [64 d][64 s]

// ---- smem (from 1KB-aligned base) ----
#define OFF_A0   0u        // Q hi | W hi (16K bf16 [128][64])
#define OFF_A1   16384u    // Q lo | W lo
#define OFF_B    32768u    // 2 x 16K tile buffers (hi 8K + lo 8K each): K (A) / V (B)
#define OFF_DT   65536u    // D transpose tile: 128 x 65 f32 = 33280
#define OFF_MISC 98816u
#define OFF_TM    (OFF_MISC + 0u)
#define OFF_KB0   (OFF_MISC + 8u)
#define OFF_KB1   (OFF_MISC + 16u)
#define OFF_MMA0  (OFF_MISC + 24u)
#define OFF_MMA1  (OFF_MISC + 32u)
#define OFF_CONS0 (OFF_MISC + 40u)
#define OFF_CONS1 (OFF_MISC + 48u)
#define OFF_MMA2  (OFF_MISC + 56u)
#define OFF_LS    (OFF_MISC + 64u)   // float[128]
#define SMEM_BYTES (OFF_MISC + 64u + 512u + 1024u)

#define IDESC_BF16_N64 ((1u<<4)|(1u<<7)|(1u<<10)|(8u<<17)|(8u<<24))
#define SWZ(o) ((o) ^ (((o) >> 3) & 0x70u))

#if defined(__CUDA_ARCH_FEAT_SM103_ALL) || defined(__CUDA_ARCH_FEAT_SM100_ALL)
#define HAS_TC 1
#endif

__device__ __forceinline__ uint32_t smem_u32(const void* p) {
    uint32_t a;
    asm("{ .reg .u64 t; cvta.to.shared.u64 t, %1; cvt.u32.u64 %0, t; }" : "=r"(a) : "l"(p));
    return a;
}
#define MBAR_INIT(a, n) asm volatile("mbarrier.init.shared.b64 [%0], %1;" :: "r"(a), "r"(n) : "memory")
#define MBAR_ARRIVE(a)  asm volatile("mbarrier.arrive.shared.b64 _, [%0];" :: "r"(a) : "memory")
#define MBAR_EXPECT(a, b) asm volatile("mbarrier.arrive.expect_tx.shared.b64 _, [%0], %1;" :: "r"(a), "r"(b) : "memory")
#define MBAR_WAIT(a, ph) do { \
    uint32_t _m = (a), _p = (ph), _d; \
    asm volatile("{ .reg .pred p; mbarrier.try_wait.parity.acquire.cta.shared::cta.b64 p, [%1], %2; selp.b32 %0,1,0,p; }" \
        : "=r"(_d) : "r"(_m), "r"(_p) : "memory"); \
    if (!_d) { \
        asm volatile("{ .reg .pred P1;\nWL_%=:\n mbarrier.try_wait.parity.acquire.cta.shared::cta.b64 P1, [%0], %1, 0x989680;\n @P1 bra.uni WD_%=;\n bra.uni WL_%=;\nWD_%=:\n}" \
            :: "r"(_m), "r"(_p) : "memory"); \
    } } while (0)
#define FENCE_ASYNC() asm volatile("fence.proxy.async.shared::cta;" ::: "memory")
#define BULK_G2S(dst, src, bytes, bar) \
    asm volatile("cp.async.bulk.shared::cluster.global.mbarrier::complete_tx::bytes [%0], [%1], %2, [%3];" \
        :: "r"(dst), "l"(src), "r"(bytes), "r"(bar) : "memory")

#ifdef HAS_TC
#define TC_ALLOC(a, n) asm volatile("tcgen05.alloc.cta_group::1.sync.aligned.shared::cta.b32 [%0], %1;" :: "r"(a), "r"(n) : "memory")
#define TC_RELINQ()    asm volatile("tcgen05.relinquish_alloc_permit.cta_group::1.sync.aligned;")
#define TC_DEALLOC(t, n) asm volatile("tcgen05.dealloc.cta_group::1.sync.aligned.b32 %0, %1;" :: "r"(t), "r"(n))
#define TC_COMMIT(bar) asm volatile("tcgen05.commit.cta_group::1.mbarrier::arrive::one.shared::cluster.b64 [%0];" :: "r"(bar) : "memory")
#define TC_WAIT_LD() asm volatile("tcgen05.wait::ld.sync.aligned;" ::: "memory")
#define TC_FENCE_BEFORE() asm volatile("tcgen05.fence::before_thread_sync;" ::: "memory")
#define TC_FENCE_AFTER()  asm volatile("tcgen05.fence::after_thread_sync;" ::: "memory")
#define TC_LD_X32(r, addr) \
    asm volatile("tcgen05.ld.sync.aligned.32x32b.x32.b32 " \
        "{%0,%1,%2,%3,%4,%5,%6,%7,%8,%9,%10,%11,%12,%13,%14,%15," \
        "%16,%17,%18,%19,%20,%21,%22,%23,%24,%25,%26,%27,%28,%29,%30,%31}, [%32];" \
        : "=r"((r)[0]),"=r"((r)[1]),"=r"((r)[2]),"=r"((r)[3]),"=r"((r)[4]),"=r"((r)[5]),"=r"((r)[6]),"=r"((r)[7]), \
          "=r"((r)[8]),"=r"((r)[9]),"=r"((r)[10]),"=r"((r)[11]),"=r"((r)[12]),"=r"((r)[13]),"=r"((r)[14]),"=r"((r)[15]), \
          "=r"((r)[16]),"=r"((r)[17]),"=r"((r)[18]),"=r"((r)[19]),"=r"((r)[20]),"=r"((r)[21]),"=r"((r)[22]),"=r"((r)[23]), \
          "=r"((r)[24]),"=r"((r)[25]),"=r"((r)[26]),"=r"((r)[27]),"=r"((r)[28]),"=r"((r)[29]),"=r"((r)[30]),"=r"((r)[31]) \
        : "r"(addr))

__device__ __forceinline__ void mma_bf16_ss(uint32_t d, uint64_t a, uint64_t b, uint32_t en) {
    asm volatile("{\n\t.reg .pred p;\n\tsetp.ne.u32 p, %4, 0;\n\t"
                 "tcgen05.mma.cta_group::1.kind::f16 [%0], %1, %2, %3, {%5,%5,%5,%5}, p;\n\t}"
                 :: "r"(d), "l"(a), "l"(b), "r"(IDESC_BF16_N64), "r"(en), "r"(0u) : "memory");
}
#endif

static __device__ __forceinline__ uint64_t mk_desc(uint32_t addr) {
    return (uint64_t(2) << 61) | (uint64_t(1) << 46) | (uint64_t(64) << 32) | (uint64_t(1) << 16)
         | ((uint64_t)(addr >> 4) & 0x3FFFull);
}

#ifdef HAS_TC
// 3-term bf16x3 MMA: A0B0 + A0B1 + A1B0, K=64 via 4 steps of 16
__device__ __forceinline__ void issue_mma3(uint32_t dtm, uint32_t a0, uint32_t a1,
                                           uint32_t b0, uint32_t b1, uint32_t accum_first) {
    uint64_t A0 = mk_desc(a0), A1 = mk_desc(a1), B0 = mk_desc(b0), B1 = mk_desc(b1);
    #pragma unroll
    for (int t = 0; t < 4; t++) mma_bf16_ss(dtm, A0 + t*2, B0 + t*2, (t > 0) ? 1u : accum_first);
    #pragma unroll
    for (int t = 0; t < 4; t++) mma_bf16_ss(dtm, A0 + t*2, B1 + t*2, 1u);
    #pragma unroll
    for (int t = 0; t < 4; t++) mma_bf16_ss(dtm, A1 + t*2, B0 + t*2, 1u);
}
#endif

__device__ __forceinline__ void cvt2(float x, float y, uint32_t& hw, uint32_t& lw) {
    __nv_bfloat162 h = __floats2bfloat162_rn(x, y);
    float hx = __bfloat162float(h.x), hy = __bfloat162float(h.y);
    __nv_bfloat162 l = __floats2bfloat162_rn(x - hx, y - hy);
    hw = *(uint32_t*)&h;
    lw = *(uint32_t*)&l;
}
__device__ __forceinline__ void stage4(float4 f, char* p0, char* p1, uint32_t off) {
    uint32_t h0, l0, h1, l1;
    cvt2(f.x, f.y, h0, l0);
    cvt2(f.z, f.w, h1, l1);
    uint32_t so = SWZ(off);
    *(uint2*)(p0 + so) = make_uint2(h0, h1);
    *(uint2*)(p1 + so) = make_uint2(l0, l1);
}

// ===================== pre-pass: K/V -> swizzled bf16 hi/lo tiles =====================
__global__ void prep_kv(const float* __restrict__ k, const float* __restrict__ v) {
    __shared__ uint8_t tile[16384];     // hi [0,8K), lo [8K,16K)
    const int c = blockIdx.x, which = blockIdx.y, bh = blockIdx.z;
    const int tid = threadIdx.x;
    if (which == 0) {
        const float4* k4 = (const float4*)(k + (size_t)bh * D_ * S_);
        for (int i = tid; i < 1024; i += 256) {
            int d = i >> 4, sq = i & 15;
            float4 f = k4[d * (S_/4) + c * 16 + sq];
            float vals[4] = {f.x, f.y, f.z, f.w};
            #pragma unroll
            for (int e = 0; e < 4; e++) {
                int s = sq * 4 + e;
                uint32_t off = SWZ((uint32_t)(s * 128 + d * 2));
                __nv_bfloat16 h = __float2bfloat16(vals[e]);
                __nv_bfloat16 l = __float2bfloat16(vals[e] - __bfloat162float(h));
                *(uint16_t*)(tile + off)        = *(uint16_t*)&h;
                *(uint16_t*)(tile + 8192 + off) = *(uint16_t*)&l;
            }
        }
        __syncthreads();
        uint4* dst = g_Kst + ((size_t)bh * NCH + c) * 1024;
        const uint4* t4 = (const uint4*)tile;
        for (int i = tid; i < 1024; i += 256) dst[i] = t4[i];
    } else {
        const float4* v4 = (const float4*)(v + (size_t)bh * S_ * D_);
        for (int i = tid; i < 1024; i += 256) {
            int s = i >> 4, dq = i & 15;
            float4 f = v4[(c * 64 + s) * (D_/4) + dq];
            float vals[4] = {f.x, f.y, f.z, f.w};
            #pragma unroll
            for (int e = 0; e < 4; e++) {
                int d = dq * 4 + e;
                uint32_t off = SWZ((uint32_t)(d * 128 + s * 2));
                __nv_bfloat16 h = __float2bfloat16(vals[e]);
                __nv_bfloat16 l = __float2bfloat16(vals[e] - __bfloat162float(h));
                *(uint16_t*)(tile + off)        = *(uint16_t*)&h;
                *(uint16_t*)(tile + 8192 + off) = *(uint16_t*)&l;
            }
        }
        __syncthreads();
        uint4* dst = g_Vst + ((size_t)bh * NCH + c) * 1024;
        const uint4* t4 = (const uint4*)tile;
        for (int i = tid; i < 1024; i += 256) dst[i] = t4[i];
    }
}

// ===================== main fused attention =====================
__global__ void __launch_bounds__(NT, 2)
attn_main(const float* __restrict__ q, const float* __restrict__ prev,
          const float* __restrict__ mask, const float* __restrict__ scale_p,
          float* __restrict__ out)
{
#ifdef HAS_TC
    extern __shared__ char smraw[];
    const uint32_t sb0 = smem_u32(smraw);
    const uint32_t sbase = (sb0 + 1023u) & ~1023u;
    char* sm = smraw + (sbase - sb0);

    const int tid = threadIdx.x;
    const int wid = tid >> 5;
    const int wg  = wid >> 2;
    const int r   = ((wid & 3) << 5) | (tid & 31);
    const int half = (tid & 31) >> 4;
    const int cl   = tid & 15;
    const int bh  = blockIdx.x >> 3;
    const int qb  = (blockIdx.x & 7) * 128;
    const float scale = *scale_p;

    float* outO = out;
    float* outW = out + OUT_O;
    float* outS = outW + OUT_W;
    float* lsum = (float*)(sm + OFF_LS);
    float* dt   = (float*)(sm + OFF_DT);

    const float4* qp4 = (const float4*)(q + ((size_t)bh * S_ + qb) * D_);
    const char* kst = (const char*)(g_Kst + (size_t)bh * NCH * 1024);
    const char* vst = (const char*)(g_Vst + (size_t)bh * NCH * 1024);

    if (tid == 0) {
        MBAR_INIT(sbase + OFF_KB0, 1);
        MBAR_INIT(sbase + OFF_KB1, 1);
        MBAR_INIT(sbase + OFF_MMA0, 1);
        MBAR_INIT(sbase + OFF_MMA1, 1);
        MBAR_INIT(sbase + OFF_CONS0, NT);
        MBAR_INIT(sbase + OFF_CONS1, NT);
        MBAR_INIT(sbase + OFF_MMA2, 1);
    }
    if (tid < 128) lsum[tid] = 0.0f;
    if (wid == 0) { TC_ALLOC(sbase + OFF_TM, 256); TC_RELINQ(); }
    __syncthreads();
    uint32_t tmem;
    asm volatile("ld.shared.b32 %0, [%1];" : "=r"(tmem) : "r"(sbase + OFF_TM));
    const uint32_t TM_D = tmem;
    const uint32_t TM_O = tmem + 128;

    // bulk-load K chunks 0,1 (tid0); stage Q (all threads)
    if (tid == 0) {
        MBAR_EXPECT(sbase + OFF_KB0, 16384);
        BULK_G2S(sbase + OFF_B, kst, 16384, sbase + OFF_KB0);
        MBAR_EXPECT(sbase + OFF_KB1, 16384);
        BULK_G2S(sbase + OFF_B + 16384u, kst + 16384, 16384, sbase + OFF_KB1);
    }
    #pragma unroll
    for (int j = 0; j < 8; j++) {
        int i = tid + j * NT;
        stage4(qp4[i], sm + OFF_A0, sm + OFF_A1, (uint32_t)i * 8u);
    }
    FENCE_ASYNC();
    __syncthreads();

    int phm0 = 0, phm1 = 0, phc0 = 0, phc1 = 0;

    // =============== Phase A ===============
    for (int c = 0; c <= NCH; c++) {
        if (c < NCH && tid == 0) {
            const int b = c & 1;
            MBAR_WAIT(sbase + (b ? OFF_KB1 : OFF_KB0), (c >> 1) & 1);
            if (c >= 2) {
                if (b == 0) { MBAR_WAIT(sbase + OFF_CONS0, phc0); phc0 ^= 1; }
                else        { MBAR_WAIT(sbase + OFF_CONS1, phc1); phc1 ^= 1; }
            }
            issue_mma3(TM_D + (uint32_t)b * 64u, sbase + OFF_A0, sbase + OFF_A1,
                       sbase + OFF_B + (uint32_t)b * 16384u,
                       sbase + OFF_B + (uint32_t)b * 16384u + 8192u, 0u);
            TC_COMMIT(sbase + (b ? OFF_MMA1 : OFF_MMA0));
        }
        if (c >= 1) {
            const int cc = c - 1, b2 = cc & 1;
            // issue prev loads before the MMA wait (latency absorbed)
            float4 pv[8];
            {
                size_t colb = (size_t)cc * 64 + cl * 4;
                #pragma unroll
                for (int j = 0; j < 8; j++) {
                    int rr = wid * 16 + 2 * j + half;
                    pv[j] = *(const float4*)(prev + ((size_t)bh * S_ + qb + rr) * S_ + colb);
                }
            }
            if (b2 == 0) { MBAR_WAIT(sbase + OFF_MMA0, phm0); phm0 ^= 1; }
            else         { MBAR_WAIT(sbase + OFF_MMA1, phm1); phm1 ^= 1; }
            if (tid == 0) {
                if (cc + 2 < NCH) {      // refill K(cc+2) into freed buf
                    uint32_t kb = sbase + ((cc & 1) ? OFF_KB1 : OFF_KB0);
                    MBAR_EXPECT(kb, 16384);
                    BULK_G2S(sbase + OFF_B + (uint32_t)(cc & 1) * 16384u,
                             kst + (size_t)(cc + 2) * 16384, 16384, kb);
                } else {                 // pre-issue Phase-B V tiles into freed bufs
                    uint32_t vb = sbase + ((cc == 14) ? OFF_KB0 : OFF_KB1);
                    int vidx = (cc == 14) ? 0 : 1;          // idx0->chunk15, idx1->chunk14
                    MBAR_EXPECT(vb, 16384);
                    BULK_G2S(sbase + OFF_B + (uint32_t)(vidx & 1) * 16384u,
                             vst + (size_t)(15 - vidx) * 16384, 16384, vb);
                }
            }
            TC_FENCE_AFTER();
            uint32_t dr[32];
            TC_LD_X32(dr, TM_D + (uint32_t)b2 * 64u + (uint32_t)wg * 32u);
            TC_WAIT_LD();
            TC_FENCE_BEFORE();
            MBAR_ARRIVE(sbase + (b2 ? OFF_CONS1 : OFF_CONS0));
            __syncthreads();            // previous epilogue's dt readers drained
            #pragma unroll
            for (int i = 0; i < 32; i++)
                dt[r * 65 + wg * 32 + i] = __uint_as_float(dr[i]);
            __syncthreads();
            #pragma unroll
            for (int j = 0; j < 8; j++) {
                int rr = wid * 16 + 2 * j + half;
                size_t gr = (size_t)bh * S_ + qb + rr;
                size_t colb = (size_t)cc * 64 + cl * 4;
                float4 mk = *(const float4*)(mask + (size_t)(qb + rr) * S_ + colb);
                int db = rr * 65 + cl * 4;
                float4 s;
                s.x = dt[db + 0] * mk.x * scale + pv[j].x;
                s.y = dt[db + 1] * mk.y * scale + pv[j].y;
                s.z = dt[db + 2] * mk.z * scale + pv[j].z;
                s.w = dt[db + 3] * mk.w * scale + pv[j].w;
                *(float4*)(outS + gr * S_ + colb) = s;
                float val = __expf(s.x) + __expf(s.y) + __expf(s.z) + __expf(s.w);
                val += __shfl_xor_sync(0xffffffffu, val, 1);
                val += __shfl_xor_sync(0xffffffffu, val, 2);
                val += __shfl_xor_sync(0xffffffffu, val, 4);
                val += __shfl_xor_sync(0xffffffffu, val, 8);
                if (cl == 0) lsum[rr] += val;
            }
        }
    }

    __syncthreads();
    if (tid < 128) lsum[tid] = 1.0f / lsum[tid];
    __syncthreads();

    // =============== Phase B: reverse chunk order ===============
    float4 sreg[8];
    #pragma unroll
    for (int j = 0; j < 8; j++) {
        int rr = wid * 16 + 2 * j + half;
        sreg[j] = *(const float4*)(outS + ((size_t)bh * S_ + qb + rr) * S_ + 15 * 64 + cl * 4);
    }
    int ph2 = 0;
    for (int idx = 0; idx < NCH; idx++) {
        const int c = 15 - idx;
        float4 wv[8];
        #pragma unroll
        for (int j = 0; j < 8; j++) {
            int rr = wid * 16 + 2 * j + half;
            float il = lsum[rr];
            wv[j].x = __expf(sreg[j].x) * il;
            wv[j].y = __expf(sreg[j].y) * il;
            wv[j].z = __expf(sreg[j].z) * il;
            wv[j].w = __expf(sreg[j].w) * il;
            *(float4*)(outW + ((size_t)bh * S_ + qb + rr) * S_ + c * 64 + cl * 4) = wv[j];
        }
        if (idx > 0) { MBAR_WAIT(sbase + OFF_MMA2, ph2); ph2 ^= 1; }
        if (tid == 0 && idx >= 1 && idx + 1 < NCH) {   // refill V(idx+1)
            uint32_t vb = sbase + (((idx + 1) & 1) ? OFF_KB1 : OFF_KB0);
            MBAR_EXPECT(vb, 16384);
            BULK_G2S(sbase + OFF_B + (uint32_t)((idx + 1) & 1) * 16384u,
                     vst + (size_t)(15 - (idx + 1)) * 16384, 16384, vb);
        }
        #pragma unroll
        for (int j = 0; j < 8; j++) {
            int rr = wid * 16 + 2 * j + half;
            stage4(wv[j], sm + OFF_A0, sm + OFF_A1, (uint32_t)rr * 128u + (uint32_t)cl * 8u);
        }
        if (idx + 1 < NCH) {
            #pragma unroll
            for (int j = 0; j < 8; j++) {
                int rr = wid * 16 + 2 * j + half;
                sreg[j] = *(const float4*)(outS + ((size_t)bh * S_ + qb + rr) * S_ + (c - 1) * 64 + cl * 4);
            }
        }
        FENCE_ASYNC();
        __syncthreads();
        if (tid == 0) {
            MBAR_WAIT(sbase + ((idx & 1) ? OFF_KB1 : OFF_KB0), (idx >> 1) & 1);
            issue_mma3(TM_O, sbase + OFF_A0, sbase + OFF_A1,
                       sbase + OFF_B + (uint32_t)(idx & 1) * 16384u,
                       sbase + OFF_B + (uint32_t)(idx & 1) * 16384u + 8192u,
                       (idx == 0) ? 0u : 1u);
            TC_COMMIT(sbase + OFF_MMA2);
        }
    }

    // =============== O writeback ===============
    MBAR_WAIT(sbase + OFF_MMA2, ph2);
    TC_FENCE_AFTER();
    {
        uint32_t o[32];
        TC_LD_X32(o, TM_O + (uint32_t)wg * 32u);
        TC_WAIT_LD();
        float4* oo = (float4*)(outO + ((size_t)bh * S_ + qb + r) * D_ + wg * 32);
        #pragma unroll
        for (int j = 0; j < 8; j++)
            oo[j] = make_float4(__uint_as_float(o[4*j]), __uint_as_float(o[4*j+1]),
                                __uint_as_float(o[4*j+2]), __uint_as_float(o[4*j+3]));
    }
    TC_FENCE_BEFORE();
    __syncthreads();
    if (wid == 0) TC_DEALLOC(tmem, 256);
#endif  // HAS_TC
}

extern "C" void kernel_launch(void* const* d_in, const int* in_sizes, int n_in,
                              void* d_out, int out_size)
{
    const float* q     = (const float*)d_in[0];
    const float* k     = (const float*)d_in[1];
    const float* v     = (const float*)d_in[2];
    const float* prev  = (const float*)d_in[3];
    const float* mask  = (const float*)d_in[4];
    const float* scale = (const float*)d_in[5];
    float* out = (float*)d_out;

    dim3 pg(NCH, 2, BH_);
    prep_kv<<<pg, 256>>>(k, v);

    cudaFuncSetAttribute(attn_main, cudaFuncAttributeMaxDynamicSharedMemorySize, SMEM_BYTES);
    attn_main<<<BH_ * 8, NT, SMEM_BYTES>>>(q, prev, mask, scale, out);
}